// round 1
// baseline (speedup 1.0000x reference)
#include <cuda_runtime.h>
#include <math.h>

// Problem constants
#define T_TOK 8192
#define DIM   1024
#define NEXP  8
#define HID   4096
#define MAXROWS 17408           // 16384 + 8*128 padding worst case
#define MAXMT   (MAXROWS / 128) // 136

// ---------------- device scratch (static allocation; no cudaMalloc) --------
__device__ float g_xn[(size_t)T_TOK * DIM];      // layernormed tokens (fp32)
__device__ float g_h [(size_t)MAXROWS * HID];    // gelu(x@W1+b1), permuted rows
__device__ float g_y [(size_t)MAXROWS * DIM];    // h@W2+b2, permuted rows
__device__ int   g_perm[MAXROWS];                // permuted row -> token (-1 = pad)
__device__ int   g_inv [T_TOK * 2];              // (token,slot) -> permuted row
__device__ float g_gw  [T_TOK * 2];              // gate weights per slot
__device__ int   g_gi  [T_TOK * 2];              // expert ids per slot
__device__ int   g_counts[NEXP];
__device__ int   g_off[NEXP + 1];
__device__ int   g_cursor[NEXP];

// ---------------- small helpers -------------------------------------------
__device__ __forceinline__ float to_tf32(float f) {
    unsigned u;
    asm("cvt.rna.tf32.f32 %0, %1;" : "=r"(u) : "f"(f));
    return __uint_as_float(u);
}

__device__ __forceinline__ void mma_tf32(float* c, const unsigned* a, const unsigned* b) {
    asm volatile(
        "mma.sync.aligned.m16n8k8.row.col.f32.tf32.tf32.f32 "
        "{%0,%1,%2,%3}, {%4,%5,%6,%7}, {%8,%9}, {%0,%1,%2,%3};\n"
        : "+f"(c[0]), "+f"(c[1]), "+f"(c[2]), "+f"(c[3])
        : "r"(a[0]), "r"(a[1]), "r"(a[2]), "r"(a[3]), "r"(b[0]), "r"(b[1]));
}

// ---------------- init: zero counters -------------------------------------
__global__ void init_kernel() {
    int i = threadIdx.x;
    if (i < NEXP) { g_counts[i] = 0; }
}

// ---------------- LayerNorm: one block per token ---------------------------
__global__ void ln_kernel(const float* __restrict__ x,
                          const float* __restrict__ gamma,
                          const float* __restrict__ beta) {
    int t = blockIdx.x;
    int tid = threadIdx.x;   // 256 threads, each one float4 (covers 1024 elems)
    const float4 v = *reinterpret_cast<const float4*>(x + (size_t)t * DIM + tid * 4);

    __shared__ float red1[8], red2[8];

    float s = v.x + v.y + v.z + v.w;
    #pragma unroll
    for (int o = 16; o; o >>= 1) s += __shfl_xor_sync(0xffffffffu, s, o);
    if ((tid & 31) == 0) red1[tid >> 5] = s;
    __syncthreads();
    float mu = 0.f;
    #pragma unroll
    for (int i = 0; i < 8; i++) mu += red1[i];
    mu *= (1.f / DIM);

    float dx = v.x - mu, dy = v.y - mu, dz = v.z - mu, dw = v.w - mu;
    float s2 = dx * dx + dy * dy + dz * dz + dw * dw;
    #pragma unroll
    for (int o = 16; o; o >>= 1) s2 += __shfl_xor_sync(0xffffffffu, s2, o);
    if ((tid & 31) == 0) red2[tid >> 5] = s2;
    __syncthreads();
    float var = 0.f;
    #pragma unroll
    for (int i = 0; i < 8; i++) var += red2[i];
    var *= (1.f / DIM);
    float rstd = rsqrtf(var + 1e-5f);

    const float4 g = *reinterpret_cast<const float4*>(gamma + tid * 4);
    const float4 b = *reinterpret_cast<const float4*>(beta  + tid * 4);
    float4 o;
    o.x = dx * rstd * g.x + b.x;
    o.y = dy * rstd * g.y + b.y;
    o.z = dz * rstd * g.z + b.z;
    o.w = dw * rstd * g.w + b.w;
    *reinterpret_cast<float4*>(g_xn + (size_t)t * DIM + tid * 4) = o;
}

// ---------------- Gating: one warp per token -------------------------------
__global__ void gate_kernel(const float* __restrict__ gw) {
    int warp = (blockIdx.x * blockDim.x + threadIdx.x) >> 5;
    int lane = threadIdx.x & 31;
    if (warp >= T_TOK) return;

    float acc[NEXP];
    #pragma unroll
    for (int e = 0; e < NEXP; e++) acc[e] = 0.f;

    const float* xr = g_xn + (size_t)warp * DIM;
    for (int d = lane; d < DIM; d += 32) {
        float xv = xr[d];
        #pragma unroll
        for (int e = 0; e < NEXP; e++) acc[e] += xv * gw[e * DIM + d];
    }
    #pragma unroll
    for (int e = 0; e < NEXP; e++)
        #pragma unroll
        for (int o = 16; o; o >>= 1) acc[e] += __shfl_xor_sync(0xffffffffu, acc[e], o);

    if (lane == 0) {
        int i0 = 0; float v0 = acc[0];
        #pragma unroll
        for (int e = 1; e < NEXP; e++) if (acc[e] > v0) { v0 = acc[e]; i0 = e; }
        int i1 = -1; float v1 = -3.0e38f;
        #pragma unroll
        for (int e = 0; e < NEXP; e++) if (e != i0 && acc[e] > v1) { v1 = acc[e]; i1 = e; }
        float ex = expf(v1 - v0);
        float g0 = 1.f / (1.f + ex);
        float g1 = ex / (1.f + ex);
        g_gi[2 * warp]     = i0;  g_gi[2 * warp + 1] = i1;
        g_gw[2 * warp]     = g0;  g_gw[2 * warp + 1] = g1;
        atomicAdd(&g_counts[i0], 1);
        atomicAdd(&g_counts[i1], 1);
    }
}

// ---------------- Scan: padded offsets -------------------------------------
__global__ void scan_kernel() {
    if (threadIdx.x == 0) {
        int o = 0;
        for (int e = 0; e < NEXP; e++) {
            g_off[e] = o;
            g_cursor[e] = o;
            o += ((g_counts[e] + 127) >> 7) << 7;
        }
        g_off[NEXP] = o;
    }
}

__global__ void fill_kernel() {
    int i = blockIdx.x * blockDim.x + threadIdx.x;
    if (i < MAXROWS) g_perm[i] = -1;
}

__global__ void scatter_kernel() {
    int t = blockIdx.x * blockDim.x + threadIdx.x;
    if (t >= T_TOK) return;
    #pragma unroll
    for (int s = 0; s < 2; s++) {
        int e = g_gi[2 * t + s];
        int pos = atomicAdd(&g_cursor[e], 1);
        g_perm[pos] = t;
        g_inv[2 * t + s] = pos;
    }
}

// ---------------- Grouped GEMM (tf32 mma.sync, 128x128x16 tiles) -----------
// MODE 1: A = gather(g_xn, perm), C = g_h with GELU epilogue. K=1024, N=4096.
// MODE 2: A = g_h (direct rows),  C = g_y, plain bias.       K=4096, N=1024.
template <int MODE>
__global__ __launch_bounds__(256)
void gemm_kernel(const float* __restrict__ Bw, const float* __restrict__ bias,
                 int Kdim, int Ncols) {
    __shared__ float As[2][128][20];   // [m][k], pad -> stride 20 (conflict-free frags)
    __shared__ float Bs[2][16][136];   // [k][n], pad -> stride 136 (8k+n banks)

    const int base = blockIdx.y * 128;
    if (base >= g_off[NEXP]) return;
    int e = 0;
    while (base >= g_off[e + 1]) e++;
    const int rows_valid = g_off[e] + g_counts[e] - base;
    if (rows_valid <= 0) return;

    const int tid  = threadIdx.x;
    const int lane = tid & 31;
    const int wid  = tid >> 5;
    const int wm = wid & 3;        // 4 warps along M (32 rows each)
    const int wn = wid >> 2;       // 2 warps along N (64 cols each)
    const int grp = lane >> 2, ctid = lane & 3;

    const int ncolbase = blockIdx.x * 128;
    const float* Bexp = Bw + (size_t)e * Kdim * Ncols;

    // A loader mapping: 2 threads per row, 8 floats each
    const int ar = tid >> 1;
    const int ak = (tid & 1) * 8;
    int arow;
    const float* Asrc;
    int lda;
    if (MODE == 1) { arow = g_perm[base + ar]; Asrc = g_xn; lda = DIM; }
    else           { arow = base + ar;         Asrc = g_h;  lda = HID; }

    // B loader mapping: 16 threads per row-group, 8 floats each
    const int bk = tid >> 4;
    const int bn = (tid & 15) * 8;

    float acc[2][8][4];
    #pragma unroll
    for (int i = 0; i < 2; i++)
        #pragma unroll
        for (int j = 0; j < 8; j++)
            #pragma unroll
            for (int q = 0; q < 4; q++) acc[i][j][q] = 0.f;

    const int nchunks = Kdim / 16;

    // prologue: stage chunk 0
    {
        float4 a0 = make_float4(0.f, 0.f, 0.f, 0.f), a1 = a0;
        if (!(MODE == 1 && arow < 0)) {
            const float* p = Asrc + (size_t)arow * lda + ak;
            a0 = *reinterpret_cast<const float4*>(p);
            a1 = *reinterpret_cast<const float4*>(p + 4);
        }
        float4 ta = make_float4(to_tf32(a0.x), to_tf32(a0.y), to_tf32(a0.z), to_tf32(a0.w));
        float4 tb = make_float4(to_tf32(a1.x), to_tf32(a1.y), to_tf32(a1.z), to_tf32(a1.w));
        *reinterpret_cast<float4*>(&As[0][ar][ak])     = ta;
        *reinterpret_cast<float4*>(&As[0][ar][ak + 4]) = tb;

        const float* q = Bexp + (size_t)bk * Ncols + ncolbase + bn;
        float4 b0 = *reinterpret_cast<const float4*>(q);
        float4 b1 = *reinterpret_cast<const float4*>(q + 4);
        float4 tc = make_float4(to_tf32(b0.x), to_tf32(b0.y), to_tf32(b0.z), to_tf32(b0.w));
        float4 td = make_float4(to_tf32(b1.x), to_tf32(b1.y), to_tf32(b1.z), to_tf32(b1.w));
        *reinterpret_cast<float4*>(&Bs[0][bk][bn])     = tc;
        *reinterpret_cast<float4*>(&Bs[0][bk][bn + 4]) = td;
    }
    __syncthreads();

    int buf = 0;
    for (int kc = 0; kc < nchunks; kc++) {
        float4 ra0, ra1, rb0, rb1;
        const bool has_next = (kc + 1 < nchunks);
        if (has_next) {
            ra0 = make_float4(0.f, 0.f, 0.f, 0.f); ra1 = ra0;
            if (!(MODE == 1 && arow < 0)) {
                const float* p = Asrc + (size_t)arow * lda + (kc + 1) * 16 + ak;
                ra0 = *reinterpret_cast<const float4*>(p);
                ra1 = *reinterpret_cast<const float4*>(p + 4);
            }
            const float* q = Bexp + (size_t)((kc + 1) * 16 + bk) * Ncols + ncolbase + bn;
            rb0 = *reinterpret_cast<const float4*>(q);
            rb1 = *reinterpret_cast<const float4*>(q + 4);
        }

        // compute current chunk (two k=8 steps)
        #pragma unroll
        for (int ks = 0; ks < 2; ks++) {
            const int k0 = ks * 8;
            unsigned afr[2][4], bfr[8][2];
            #pragma unroll
            for (int i = 0; i < 2; i++) {
                const int r = wm * 32 + i * 16;
                afr[i][0] = __float_as_uint(As[buf][r + grp][k0 + ctid]);
                afr[i][1] = __float_as_uint(As[buf][r + grp + 8][k0 + ctid]);
                afr[i][2] = __float_as_uint(As[buf][r + grp][k0 + ctid + 4]);
                afr[i][3] = __float_as_uint(As[buf][r + grp + 8][k0 + ctid + 4]);
            }
            #pragma unroll
            for (int j = 0; j < 8; j++) {
                const int c = wn * 64 + j * 8 + grp;
                bfr[j][0] = __float_as_uint(Bs[buf][k0 + ctid][c]);
                bfr[j][1] = __float_as_uint(Bs[buf][k0 + ctid + 4][c]);
            }
            #pragma unroll
            for (int i = 0; i < 2; i++)
                #pragma unroll
                for (int j = 0; j < 8; j++)
                    mma_tf32(acc[i][j], afr[i], bfr[j]);
        }

        if (has_next) {
            const int nb = buf ^ 1;
            float4 ta = make_float4(to_tf32(ra0.x), to_tf32(ra0.y), to_tf32(ra0.z), to_tf32(ra0.w));
            float4 tb = make_float4(to_tf32(ra1.x), to_tf32(ra1.y), to_tf32(ra1.z), to_tf32(ra1.w));
            *reinterpret_cast<float4*>(&As[nb][ar][ak])     = ta;
            *reinterpret_cast<float4*>(&As[nb][ar][ak + 4]) = tb;
            float4 tc = make_float4(to_tf32(rb0.x), to_tf32(rb0.y), to_tf32(rb0.z), to_tf32(rb0.w));
            float4 td = make_float4(to_tf32(rb1.x), to_tf32(rb1.y), to_tf32(rb1.z), to_tf32(rb1.w));
            *reinterpret_cast<float4*>(&Bs[nb][bk][bn])     = tc;
            *reinterpret_cast<float4*>(&Bs[nb][bk][bn + 4]) = td;
            __syncthreads();
            buf = nb;
        }
    }

    // epilogue
    #pragma unroll
    for (int i = 0; i < 2; i++) {
        const int r0 = wm * 32 + i * 16 + grp;
        #pragma unroll
        for (int j = 0; j < 8; j++) {
            const int c = wn * 64 + j * 8 + ctid * 2;
            const int ng = ncolbase + c;
            const float bv0 = bias[ng], bv1 = bias[ng + 1];

            if (r0 < rows_valid) {
                const int pos = base + r0;
                float v0 = acc[i][j][0] + bv0;
                float v1 = acc[i][j][1] + bv1;
                if (MODE == 1) {
                    v0 *= normcdff(v0); v1 *= normcdff(v1);
                    g_h[(size_t)pos * HID + ng]     = v0;
                    g_h[(size_t)pos * HID + ng + 1] = v1;
                } else {
                    g_y[(size_t)pos * DIM + ng]     = v0;
                    g_y[(size_t)pos * DIM + ng + 1] = v1;
                }
            }
            if (r0 + 8 < rows_valid) {
                const int pos = base + r0 + 8;
                float v0 = acc[i][j][2] + bv0;
                float v1 = acc[i][j][3] + bv1;
                if (MODE == 1) {
                    v0 *= normcdff(v0); v1 *= normcdff(v1);
                    g_h[(size_t)pos * HID + ng]     = v0;
                    g_h[(size_t)pos * HID + ng + 1] = v1;
                } else {
                    g_y[(size_t)pos * DIM + ng]     = v0;
                    g_y[(size_t)pos * DIM + ng + 1] = v1;
                }
            }
        }
    }
}

// ---------------- Combine: residual + gated sum ----------------------------
__global__ void combine_kernel(const float* __restrict__ x, float* __restrict__ out) {
    int t = blockIdx.x;
    int tid = threadIdx.x;
    float g0 = g_gw[2 * t], g1 = g_gw[2 * t + 1];
    int   p0 = g_inv[2 * t], p1 = g_inv[2 * t + 1];
    int idx = tid * 4;
    float4 xv = *reinterpret_cast<const float4*>(x + (size_t)t * DIM + idx);
    float4 y0 = *reinterpret_cast<const float4*>(g_y + (size_t)p0 * DIM + idx);
    float4 y1 = *reinterpret_cast<const float4*>(g_y + (size_t)p1 * DIM + idx);
    float4 o;
    o.x = xv.x + g0 * y0.x + g1 * y1.x;
    o.y = xv.y + g0 * y0.y + g1 * y1.y;
    o.z = xv.z + g0 * y0.z + g1 * y1.z;
    o.w = xv.w + g0 * y0.w + g1 * y1.w;
    *reinterpret_cast<float4*>(out + (size_t)t * DIM + idx) = o;
}

// ---------------- Balance loss: deterministic single-block reduction -------
__global__ void loss_kernel(float* __restrict__ out, int out_size) {
    __shared__ float red[256];
    __shared__ float tot[NEXP];
    int tid = threadIdx.x;
    float s[NEXP];
    #pragma unroll
    for (int q = 0; q < NEXP; q++) s[q] = 0.f;
    for (int i = tid; i < 2 * T_TOK; i += 256) {
        int e = g_gi[i];
        float w = g_gw[i];
        #pragma unroll
        for (int q = 0; q < NEXP; q++) s[q] += (e == q) ? w : 0.f;
    }
    for (int q = 0; q < NEXP; q++) {
        red[tid] = s[q];
        __syncthreads();
        for (int o = 128; o; o >>= 1) {
            if (tid < o) red[tid] += red[tid + o];
            __syncthreads();
        }
        if (tid == 0) tot[q] = red[0];
        __syncthreads();
    }
    if (tid == 0 && out_size > T_TOK * DIM) {
        float l = 0.f;
        #pragma unroll
        for (int q = 0; q < NEXP; q++) {
            float d = tot[q] * (1.f / T_TOK) - (1.f / NEXP);
            l += d * d;
        }
        out[T_TOK * DIM] = l * (1.f / NEXP);
    }
}

// ---------------- launch ----------------------------------------------------
extern "C" void kernel_launch(void* const* d_in, const int* in_sizes, int n_in,
                              void* d_out, int out_size) {
    const float* x      = (const float*)d_in[0];
    const float* gamma  = (const float*)d_in[1];
    const float* beta   = (const float*)d_in[2];
    const float* gate_w = (const float*)d_in[3];
    const float* W1     = (const float*)d_in[4];
    const float* b1     = (const float*)d_in[5];
    const float* W2     = (const float*)d_in[6];
    const float* b2     = (const float*)d_in[7];
    float* out = (float*)d_out;

    init_kernel<<<1, 32>>>();
    ln_kernel<<<T_TOK, 256>>>(x, gamma, beta);
    gate_kernel<<<T_TOK / 8, 256>>>(gate_w);
    scan_kernel<<<1, 1>>>();
    fill_kernel<<<MAXROWS / 256, 256>>>();
    scatter_kernel<<<T_TOK / 256, 256>>>();
    gemm_kernel<1><<<dim3(HID / 128, MAXMT), 256>>>(W1, b1, DIM, HID);
    gemm_kernel<2><<<dim3(DIM / 128, MAXMT), 256>>>(W2, b2, HID, DIM);
    combine_kernel<<<T_TOK, 256>>>(x, out);
    loss_kernel<<<1, 256>>>(out, out_size);
}

// round 3
// speedup vs baseline: 1.1436x; 1.1436x over previous
#include <cuda_runtime.h>
#include <math.h>
#include <stdint.h>

// Problem constants
#define T_TOK 8192
#define DIM   1024
#define NEXP  8
#define HID   4096
#define MTILE 128
#define MAXROWS 17408            // 16384 + 8*128 pad
#define MAXMT   (MAXROWS / MTILE)

// ---------------- device scratch (static; no cudaMalloc) -------------------
__device__ float g_xn [(size_t)T_TOK * DIM];     // layernorm out, fp32 (for gate)
__device__ float g_xnr[(size_t)T_TOK * DIM];     // layernorm out, tf32-rounded
__device__ float g_h  [(size_t)MAXROWS * HID];   // gelu(x@W1+b1), tf32-rounded
__device__ float g_y  [(size_t)MAXROWS * DIM];
__device__ float g_w1r[(size_t)NEXP * DIM * HID]; // tf32-rounded W1 [e][k][n]
__device__ float g_w2r[(size_t)NEXP * HID * DIM]; // tf32-rounded W2 [e][k][n]
__device__ int   g_perm[MAXROWS];
__device__ int   g_inv [T_TOK * 2];
__device__ float g_gw  [T_TOK * 2];
__device__ int   g_gi  [T_TOK * 2];
__device__ int   g_counts[NEXP];
__device__ int   g_off[NEXP + 1];
__device__ int   g_cursor[NEXP];

// ---------------- helpers ----------------------------------------------------
__device__ __forceinline__ float to_tf32(float f) {
    unsigned u;
    asm("cvt.rna.tf32.f32 %0, %1;" : "=r"(u) : "f"(f));
    return __uint_as_float(u);
}

__device__ __forceinline__ void mma_tf32(float* c, const unsigned* a, const unsigned* b) {
    asm volatile(
        "mma.sync.aligned.m16n8k8.row.col.f32.tf32.tf32.f32 "
        "{%0,%1,%2,%3}, {%4,%5,%6,%7}, {%8,%9}, {%0,%1,%2,%3};\n"
        : "+f"(c[0]), "+f"(c[1]), "+f"(c[2]), "+f"(c[3])
        : "r"(a[0]), "r"(a[1]), "r"(a[2]), "r"(a[3]), "r"(b[0]), "r"(b[1]));
}

__device__ __forceinline__ void cp_async16(uint32_t saddr, const void* gptr) {
    asm volatile("cp.async.cg.shared.global [%0], [%1], 16;"
        :: "r"(saddr), "l"(__cvta_generic_to_global(gptr)) : "memory");
}
#define CP_COMMIT() asm volatile("cp.async.commit_group;" ::: "memory")
#define CP_WAIT1()  asm volatile("cp.async.wait_group 1;"  ::: "memory")
#define CP_WAIT0()  asm volatile("cp.async.wait_group 0;"  ::: "memory")

// ---------------- init ------------------------------------------------------
__global__ void init_kernel() {
    int i = threadIdx.x;
    if (i < NEXP) g_counts[i] = 0;
}

// ---------------- weight rounding (copy, tf32 RNA) --------------------------
__global__ void round_kernel(const float* __restrict__ in, float* __restrict__ out, int n4) {
    int i = blockIdx.x * blockDim.x + threadIdx.x;
    if (i >= n4) return;
    float4 v = reinterpret_cast<const float4*>(in)[i];
    v.x = to_tf32(v.x); v.y = to_tf32(v.y); v.z = to_tf32(v.z); v.w = to_tf32(v.w);
    reinterpret_cast<float4*>(out)[i] = v;
}

// ---------------- LayerNorm --------------------------------------------------
__global__ void ln_kernel(const float* __restrict__ x,
                          const float* __restrict__ gamma,
                          const float* __restrict__ beta) {
    int t = blockIdx.x;
    int tid = threadIdx.x;
    const float4 v = *reinterpret_cast<const float4*>(x + (size_t)t * DIM + tid * 4);
    __shared__ float red1[8], red2[8];

    float s = v.x + v.y + v.z + v.w;
    #pragma unroll
    for (int o = 16; o; o >>= 1) s += __shfl_xor_sync(0xffffffffu, s, o);
    if ((tid & 31) == 0) red1[tid >> 5] = s;
    __syncthreads();
    float mu = 0.f;
    #pragma unroll
    for (int i = 0; i < 8; i++) mu += red1[i];
    mu *= (1.f / DIM);

    float dx = v.x - mu, dy = v.y - mu, dz = v.z - mu, dw = v.w - mu;
    float s2 = dx * dx + dy * dy + dz * dz + dw * dw;
    #pragma unroll
    for (int o = 16; o; o >>= 1) s2 += __shfl_xor_sync(0xffffffffu, s2, o);
    if ((tid & 31) == 0) red2[tid >> 5] = s2;
    __syncthreads();
    float var = 0.f;
    #pragma unroll
    for (int i = 0; i < 8; i++) var += red2[i];
    var *= (1.f / DIM);
    float rstd = rsqrtf(var + 1e-5f);

    const float4 g = *reinterpret_cast<const float4*>(gamma + tid * 4);
    const float4 b = *reinterpret_cast<const float4*>(beta  + tid * 4);
    float4 o;
    o.x = dx * rstd * g.x + b.x;
    o.y = dy * rstd * g.y + b.y;
    o.z = dz * rstd * g.z + b.z;
    o.w = dw * rstd * g.w + b.w;
    *reinterpret_cast<float4*>(g_xn + (size_t)t * DIM + tid * 4) = o;
    float4 r;
    r.x = to_tf32(o.x); r.y = to_tf32(o.y); r.z = to_tf32(o.z); r.w = to_tf32(o.w);
    *reinterpret_cast<float4*>(g_xnr + (size_t)t * DIM + tid * 4) = r;
}

// ---------------- Gating -----------------------------------------------------
__global__ void gate_kernel(const float* __restrict__ gw) {
    int warp = (blockIdx.x * blockDim.x + threadIdx.x) >> 5;
    int lane = threadIdx.x & 31;
    if (warp >= T_TOK) return;

    float acc[NEXP];
    #pragma unroll
    for (int e = 0; e < NEXP; e++) acc[e] = 0.f;

    const float* xr = g_xn + (size_t)warp * DIM;
    for (int d = lane; d < DIM; d += 32) {
        float xv = xr[d];
        #pragma unroll
        for (int e = 0; e < NEXP; e++) acc[e] += xv * gw[e * DIM + d];
    }
    #pragma unroll
    for (int e = 0; e < NEXP; e++)
        #pragma unroll
        for (int o = 16; o; o >>= 1) acc[e] += __shfl_xor_sync(0xffffffffu, acc[e], o);

    if (lane == 0) {
        int i0 = 0; float v0 = acc[0];
        #pragma unroll
        for (int e = 1; e < NEXP; e++) if (acc[e] > v0) { v0 = acc[e]; i0 = e; }
        int i1 = -1; float v1 = -3.0e38f;
        #pragma unroll
        for (int e = 0; e < NEXP; e++) if (e != i0 && acc[e] > v1) { v1 = acc[e]; i1 = e; }
        float ex = expf(v1 - v0);
        float g0 = 1.f / (1.f + ex);
        float g1 = ex / (1.f + ex);
        g_gi[2 * warp]     = i0;  g_gi[2 * warp + 1] = i1;
        g_gw[2 * warp]     = g0;  g_gw[2 * warp + 1] = g1;
        atomicAdd(&g_counts[i0], 1);
        atomicAdd(&g_counts[i1], 1);
    }
}

// ---------------- Scan / scatter ---------------------------------------------
__global__ void scan_kernel() {
    if (threadIdx.x == 0) {
        int o = 0;
        for (int e = 0; e < NEXP; e++) {
            g_off[e] = o;
            g_cursor[e] = o;
            o += ((g_counts[e] + (MTILE - 1)) / MTILE) * MTILE;
        }
        g_off[NEXP] = o;
    }
}

__global__ void fill_kernel() {
    int i = blockIdx.x * blockDim.x + threadIdx.x;
    if (i < MAXROWS) g_perm[i] = -1;
}

__global__ void scatter_kernel() {
    int t = blockIdx.x * blockDim.x + threadIdx.x;
    if (t >= T_TOK) return;
    #pragma unroll
    for (int s = 0; s < 2; s++) {
        int e = g_gi[2 * t + s];
        int pos = atomicAdd(&g_cursor[e], 1);
        g_perm[pos] = t;
        g_inv[2 * t + s] = pos;
    }
}

// ---------------- Grouped GEMM: tf32 mma.sync, cp.async 3-stage --------------
// Tile 128x128x32, 8 warps (4M x 2N), warp tile 32x64.
// SMEM per stage: A[128][36] floats, B[32][136] floats.
#define A_STRIDE 36
#define B_STRIDE 136
#define A_STAGE  (128 * A_STRIDE)    // floats
#define B_STAGE  (32 * B_STRIDE)
#define B_BASE   (3 * A_STAGE)
#define SMEM_FLOATS (3 * A_STAGE + 3 * B_STAGE)
#define SMEM_GEMM_BYTES (SMEM_FLOATS * 4)

template <int MODE>
__global__ void __launch_bounds__(256, 2)
gemm_mma(const float* __restrict__ Bw, const float* __restrict__ bias,
         int Kdim, int Ncols) {
    extern __shared__ __align__(16) float sm[];

    const int base = blockIdx.y * MTILE;
    if (base >= g_off[NEXP]) return;
    int e = 0;
    while (base >= g_off[e + 1]) e++;
    const int rows_valid = g_off[e] + g_counts[e] - base;
    if (rows_valid <= 0) return;

    const int tid  = threadIdx.x;
    const int lane = tid & 31;
    const int wid  = tid >> 5;
    const int wm = wid & 3;
    const int wn = wid >> 2;
    const int grp = lane >> 3;          // unused alias guard
    (void)grp;
    const int row8 = lane >> 2;         // 0..7
    const int ctid = lane & 3;          // 0..3

    const int ncolbase = blockIdx.x * 128;
    const float* Bexp = Bw + (size_t)e * Kdim * Ncols;

    // ---- A loader: 2 threads per row, 4x16B each (row = 128B per chunk)
    const int ar = tid >> 1;
    const int aseg = (tid & 1) * 4;     // segment base (each seg = 16B)
    const float* asrc;
    if (MODE == 1) {
        int tok = g_perm[base + ar];
        if (tok < 0) tok = 0;
        asrc = g_xnr + (size_t)tok * DIM;
    } else {
        asrc = g_h + (size_t)(base + ar) * HID;
    }
    const uint32_t smem_u32 = (uint32_t)__cvta_generic_to_shared(sm);
    uint32_t a_sm[4];
    #pragma unroll
    for (int i = 0; i < 4; i++)
        a_sm[i] = smem_u32 + (ar * A_STRIDE + (aseg + i) * 4) * 4;

    // ---- B loader: 8 threads per k-row, 4x16B each (row = 512B)
    const int bk = tid >> 3;            // 0..31
    const int bseg = tid & 7;           // 16B seg base, stride 8
    const float* bsrc0 = Bexp + (size_t)bk * Ncols + ncolbase;
    uint32_t b_sm[4];
    #pragma unroll
    for (int j = 0; j < 4; j++)
        b_sm[j] = smem_u32 + (B_BASE + bk * B_STRIDE + (bseg + j * 8) * 4) * 4;

    float acc[2][8][4];
    #pragma unroll
    for (int i = 0; i < 2; i++)
        #pragma unroll
        for (int j = 0; j < 8; j++)
            #pragma unroll
            for (int q = 0; q < 4; q++) acc[i][j][q] = 0.f;

    const int nch = Kdim / 32;

    // prologue: stage chunks 0 and 1
    #pragma unroll
    for (int s = 0; s < 2; s++) {
        const float* ga = asrc + s * 32 + aseg * 4;
        const float* gb = bsrc0 + (size_t)s * 32 * Ncols;
        const uint32_t ao = s * A_STAGE * 4;
        const uint32_t bo = s * B_STAGE * 4;
        #pragma unroll
        for (int i = 0; i < 4; i++) cp_async16(a_sm[i] + ao, ga + i * 4);
        #pragma unroll
        for (int j = 0; j < 4; j++) cp_async16(b_sm[j] + bo, gb + (bseg + j * 8) * 4);
        CP_COMMIT();
    }

    for (int kc = 0; kc < nch; kc++) {
        CP_WAIT1();
        __syncthreads();

        const int cl = kc + 2;
        if (cl < nch) {
            const int st2 = cl % 3;
            const float* ga = asrc + cl * 32 + aseg * 4;
            const float* gb = bsrc0 + (size_t)cl * 32 * Ncols;
            const uint32_t ao = st2 * A_STAGE * 4;
            const uint32_t bo = st2 * B_STAGE * 4;
            #pragma unroll
            for (int i = 0; i < 4; i++) cp_async16(a_sm[i] + ao, ga + i * 4);
            #pragma unroll
            for (int j = 0; j < 4; j++) cp_async16(b_sm[j] + bo, gb + (bseg + j * 8) * 4);
        }
        CP_COMMIT();

        const int st = kc % 3;
        const float* A_s = sm + st * A_STAGE;
        const float* B_s = sm + B_BASE + st * B_STAGE;
        const int g8 = lane >> 2;   // 0..7

        #pragma unroll
        for (int ks = 0; ks < 4; ks++) {
            const int k0 = ks * 8;
            unsigned afr[2][4], bfr[8][2];
            #pragma unroll
            for (int i = 0; i < 2; i++) {
                const int r = wm * 32 + i * 16;
                afr[i][0] = __float_as_uint(A_s[(r + g8)     * A_STRIDE + k0 + ctid]);
                afr[i][1] = __float_as_uint(A_s[(r + g8 + 8) * A_STRIDE + k0 + ctid]);
                afr[i][2] = __float_as_uint(A_s[(r + g8)     * A_STRIDE + k0 + ctid + 4]);
                afr[i][3] = __float_as_uint(A_s[(r + g8 + 8) * A_STRIDE + k0 + ctid + 4]);
            }
            #pragma unroll
            for (int j = 0; j < 8; j++) {
                const int c = wn * 64 + j * 8 + g8;
                bfr[j][0] = __float_as_uint(B_s[(k0 + ctid)     * B_STRIDE + c]);
                bfr[j][1] = __float_as_uint(B_s[(k0 + ctid + 4) * B_STRIDE + c]);
            }
            #pragma unroll
            for (int i = 0; i < 2; i++)
                #pragma unroll
                for (int j = 0; j < 8; j++)
                    mma_tf32(acc[i][j], afr[i], bfr[j]);
        }
    }
    CP_WAIT0();

    // ---- epilogue
    const int g8 = lane >> 2;
    #pragma unroll
    for (int i = 0; i < 2; i++) {
        const int r0 = wm * 32 + i * 16 + g8;
        #pragma unroll
        for (int j = 0; j < 8; j++) {
            const int c = wn * 64 + j * 8 + ctid * 2;
            const int ng = ncolbase + c;
            const float bv0 = bias[ng], bv1 = bias[ng + 1];

            if (r0 < rows_valid) {
                const int pos = base + r0;
                float v0 = acc[i][j][0] + bv0;
                float v1 = acc[i][j][1] + bv1;
                if (MODE == 1) {
                    v0 *= normcdff(v0); v1 *= normcdff(v1);
                    v0 = to_tf32(v0);  v1 = to_tf32(v1);
                    g_h[(size_t)pos * HID + ng]     = v0;
                    g_h[(size_t)pos * HID + ng + 1] = v1;
                } else {
                    g_y[(size_t)pos * DIM + ng]     = v0;
                    g_y[(size_t)pos * DIM + ng + 1] = v1;
                }
            }
            if (r0 + 8 < rows_valid) {
                const int pos = base + r0 + 8;
                float v0 = acc[i][j][2] + bv0;
                float v1 = acc[i][j][3] + bv1;
                if (MODE == 1) {
                    v0 *= normcdff(v0); v1 *= normcdff(v1);
                    v0 = to_tf32(v0);  v1 = to_tf32(v1);
                    g_h[(size_t)pos * HID + ng]     = v0;
                    g_h[(size_t)pos * HID + ng + 1] = v1;
                } else {
                    g_y[(size_t)pos * DIM + ng]     = v0;
                    g_y[(size_t)pos * DIM + ng + 1] = v1;
                }
            }
        }
    }
}

// ---------------- Combine ----------------------------------------------------
__global__ void combine_kernel(const float* __restrict__ x, float* __restrict__ out) {
    int t = blockIdx.x;
    int tid = threadIdx.x;
    float g0 = g_gw[2 * t], g1 = g_gw[2 * t + 1];
    int   p0 = g_inv[2 * t], p1 = g_inv[2 * t + 1];
    int idx = tid * 4;
    float4 xv = *reinterpret_cast<const float4*>(x + (size_t)t * DIM + idx);
    float4 y0 = *reinterpret_cast<const float4*>(g_y + (size_t)p0 * DIM + idx);
    float4 y1 = *reinterpret_cast<const float4*>(g_y + (size_t)p1 * DIM + idx);
    float4 o;
    o.x = xv.x + g0 * y0.x + g1 * y1.x;
    o.y = xv.y + g0 * y0.y + g1 * y1.y;
    o.z = xv.z + g0 * y0.z + g1 * y1.z;
    o.w = xv.w + g0 * y0.w + g1 * y1.w;
    *reinterpret_cast<float4*>(out + (size_t)t * DIM + idx) = o;
}

// ---------------- Balance loss -------------------------------------------------
__global__ void loss_kernel(float* __restrict__ out, int out_size) {
    __shared__ float red[256];
    __shared__ float tot[NEXP];
    int tid = threadIdx.x;
    float s[NEXP];
    #pragma unroll
    for (int q = 0; q < NEXP; q++) s[q] = 0.f;
    for (int i = tid; i < 2 * T_TOK; i += 256) {
        int e = g_gi[i];
        float w = g_gw[i];
        #pragma unroll
        for (int q = 0; q < NEXP; q++) s[q] += (e == q) ? w : 0.f;
    }
    for (int q = 0; q < NEXP; q++) {
        red[tid] = s[q];
        __syncthreads();
        for (int o = 128; o; o >>= 1) {
            if (tid < o) red[tid] += red[tid + o];
            __syncthreads();
        }
        if (tid == 0) tot[q] = red[0];
        __syncthreads();
    }
    if (tid == 0 && out_size > T_TOK * DIM) {
        float l = 0.f;
        #pragma unroll
        for (int q = 0; q < NEXP; q++) {
            float d = tot[q] * (1.f / T_TOK) - (1.f / NEXP);
            l += d * d;
        }
        out[T_TOK * DIM] = l * (1.f / NEXP);
    }
}

// ---------------- launch --------------------------------------------------------
extern "C" void kernel_launch(void* const* d_in, const int* in_sizes, int n_in,
                              void* d_out, int out_size) {
    const float* x      = (const float*)d_in[0];
    const float* gamma  = (const float*)d_in[1];
    const float* beta   = (const float*)d_in[2];
    const float* gate_w = (const float*)d_in[3];
    const float* W1     = (const float*)d_in[4];
    const float* b1     = (const float*)d_in[5];
    const float* W2     = (const float*)d_in[6];
    const float* b2     = (const float*)d_in[7];
    float* out = (float*)d_out;

    cudaFuncSetAttribute(gemm_mma<1>, cudaFuncAttributeMaxDynamicSharedMemorySize, SMEM_GEMM_BYTES);
    cudaFuncSetAttribute(gemm_mma<2>, cudaFuncAttributeMaxDynamicSharedMemorySize, SMEM_GEMM_BYTES);

    float *w1r, *w2r;
    cudaGetSymbolAddress((void**)&w1r, g_w1r);
    cudaGetSymbolAddress((void**)&w2r, g_w2r);
    const int n4 = NEXP * DIM * HID / 4;
    round_kernel<<<(n4 + 255) / 256, 256>>>(W1, w1r, n4);
    round_kernel<<<(n4 + 255) / 256, 256>>>(W2, w2r, n4);

    init_kernel<<<1, 32>>>();
    ln_kernel<<<T_TOK, 256>>>(x, gamma, beta);
    gate_kernel<<<T_TOK / 8, 256>>>(gate_w);
    scan_kernel<<<1, 1>>>();
    fill_kernel<<<(MAXROWS + 255) / 256, 256>>>();
    scatter_kernel<<<T_TOK / 256, 256>>>();

    gemm_mma<1><<<dim3(HID / 128, MAXMT), 256, SMEM_GEMM_BYTES>>>(w1r, b1, DIM, HID);
    gemm_mma<2><<<dim3(DIM / 128, MAXMT), 256, SMEM_GEMM_BYTES>>>(w2r, b2, HID, DIM);

    combine_kernel<<<T_TOK, 256>>>(x, out);
    loss_kernel<<<1, 256>>>(out, out_size);
}

// round 4
// speedup vs baseline: 1.7305x; 1.5132x over previous
#include <cuda_runtime.h>
#include <cuda_fp16.h>
#include <math.h>
#include <stdint.h>

// Problem constants
#define T_TOK 8192
#define DIM   1024
#define NEXP  8
#define HID   4096
#define MTILE 128
#define MAXROWS 17408            // 16384 + 8*128 pad
#define MAXMT   (MAXROWS / MTILE)

// ---------------- device scratch (static; no cudaMalloc) -------------------
__device__ float  g_xn [(size_t)T_TOK * DIM];      // LN out fp32 (gate)
__device__ __half g_xh [(size_t)T_TOK * DIM];      // LN out fp16 (GEMM1 A)
__device__ __half g_hh [(size_t)MAXROWS * HID];    // gelu(x@W1+b1) fp16
__device__ float  g_y  [(size_t)MAXROWS * DIM];    // h@W2+b2 fp32
__device__ __half g_w1h[(size_t)NEXP * DIM * HID]; // W1 -> [e][n(H)][k(D)] fp16
__device__ __half g_w2h[(size_t)NEXP * HID * DIM]; // W2 -> [e][n(D)][k(H)] fp16
__device__ int    g_perm[MAXROWS];
__device__ int    g_inv [T_TOK * 2];
__device__ float  g_gw  [T_TOK * 2];
__device__ int    g_gi  [T_TOK * 2];
__device__ int    g_counts[NEXP];
__device__ int    g_off[NEXP + 1];
__device__ int    g_cursor[NEXP];

// ---------------- helpers ----------------------------------------------------
__device__ __forceinline__ void mma_f16(float* c, const unsigned* a, const unsigned* b) {
    asm volatile(
        "mma.sync.aligned.m16n8k16.row.col.f32.f16.f16.f32 "
        "{%0,%1,%2,%3}, {%4,%5,%6,%7}, {%8,%9}, {%0,%1,%2,%3};\n"
        : "+f"(c[0]), "+f"(c[1]), "+f"(c[2]), "+f"(c[3])
        : "r"(a[0]), "r"(a[1]), "r"(a[2]), "r"(a[3]), "r"(b[0]), "r"(b[1]));
}

__device__ __forceinline__ void cp_async16(uint32_t saddr, const void* gptr) {
    asm volatile("cp.async.cg.shared.global [%0], [%1], 16;"
        :: "r"(saddr), "l"(__cvta_generic_to_global(gptr)) : "memory");
}
#define CP_COMMIT() asm volatile("cp.async.commit_group;" ::: "memory")
#define CP_WAIT1()  asm volatile("cp.async.wait_group 1;"  ::: "memory")
#define CP_WAIT0()  asm volatile("cp.async.wait_group 0;"  ::: "memory")

// ---------------- init ------------------------------------------------------
__global__ void init_kernel() {
    int i = threadIdx.x;
    if (i < NEXP) g_counts[i] = 0;
}

// ---------------- weight transpose+fp16: [e][k][n] f32 -> [e][n][k] f16 -----
__global__ void transpose_h_kernel(const float* __restrict__ in, __half* __restrict__ out,
                                   int K, int N) {
    __shared__ float t[32][33];
    const size_t eo = (size_t)blockIdx.z * K * N;
    const int n0 = blockIdx.x * 32, k0 = blockIdx.y * 32;
    for (int j = threadIdx.y; j < 32; j += 8)
        t[j][threadIdx.x] = in[eo + (size_t)(k0 + j) * N + n0 + threadIdx.x];
    __syncthreads();
    for (int j = threadIdx.y; j < 32; j += 8)
        out[eo + (size_t)(n0 + j) * K + k0 + threadIdx.x] = __float2half_rn(t[threadIdx.x][j]);
}

// ---------------- LayerNorm --------------------------------------------------
__global__ void ln_kernel(const float* __restrict__ x,
                          const float* __restrict__ gamma,
                          const float* __restrict__ beta) {
    int t = blockIdx.x;
    int tid = threadIdx.x;
    const float4 v = *reinterpret_cast<const float4*>(x + (size_t)t * DIM + tid * 4);
    __shared__ float red1[8], red2[8];

    float s = v.x + v.y + v.z + v.w;
    #pragma unroll
    for (int o = 16; o; o >>= 1) s += __shfl_xor_sync(0xffffffffu, s, o);
    if ((tid & 31) == 0) red1[tid >> 5] = s;
    __syncthreads();
    float mu = 0.f;
    #pragma unroll
    for (int i = 0; i < 8; i++) mu += red1[i];
    mu *= (1.f / DIM);

    float dx = v.x - mu, dy = v.y - mu, dz = v.z - mu, dw = v.w - mu;
    float s2 = dx * dx + dy * dy + dz * dz + dw * dw;
    #pragma unroll
    for (int o = 16; o; o >>= 1) s2 += __shfl_xor_sync(0xffffffffu, s2, o);
    if ((tid & 31) == 0) red2[tid >> 5] = s2;
    __syncthreads();
    float var = 0.f;
    #pragma unroll
    for (int i = 0; i < 8; i++) var += red2[i];
    var *= (1.f / DIM);
    float rstd = rsqrtf(var + 1e-5f);

    const float4 g = *reinterpret_cast<const float4*>(gamma + tid * 4);
    const float4 b = *reinterpret_cast<const float4*>(beta  + tid * 4);
    float4 o;
    o.x = dx * rstd * g.x + b.x;
    o.y = dy * rstd * g.y + b.y;
    o.z = dz * rstd * g.z + b.z;
    o.w = dw * rstd * g.w + b.w;
    *reinterpret_cast<float4*>(g_xn + (size_t)t * DIM + tid * 4) = o;

    __half2 h0 = __floats2half2_rn(o.x, o.y);
    __half2 h1 = __floats2half2_rn(o.z, o.w);
    *reinterpret_cast<__half2*>(g_xh + (size_t)t * DIM + tid * 4)     = h0;
    *reinterpret_cast<__half2*>(g_xh + (size_t)t * DIM + tid * 4 + 2) = h1;
}

// ---------------- Gating -----------------------------------------------------
__global__ void gate_kernel(const float* __restrict__ gw) {
    int warp = (blockIdx.x * blockDim.x + threadIdx.x) >> 5;
    int lane = threadIdx.x & 31;
    if (warp >= T_TOK) return;

    float acc[NEXP];
    #pragma unroll
    for (int e = 0; e < NEXP; e++) acc[e] = 0.f;

    const float* xr = g_xn + (size_t)warp * DIM;
    for (int d = lane; d < DIM; d += 32) {
        float xv = xr[d];
        #pragma unroll
        for (int e = 0; e < NEXP; e++) acc[e] += xv * gw[e * DIM + d];
    }
    #pragma unroll
    for (int e = 0; e < NEXP; e++)
        #pragma unroll
        for (int o = 16; o; o >>= 1) acc[e] += __shfl_xor_sync(0xffffffffu, acc[e], o);

    if (lane == 0) {
        int i0 = 0; float v0 = acc[0];
        #pragma unroll
        for (int e = 1; e < NEXP; e++) if (acc[e] > v0) { v0 = acc[e]; i0 = e; }
        int i1 = -1; float v1 = -3.0e38f;
        #pragma unroll
        for (int e = 0; e < NEXP; e++) if (e != i0 && acc[e] > v1) { v1 = acc[e]; i1 = e; }
        float ex = expf(v1 - v0);
        float g0 = 1.f / (1.f + ex);
        float g1 = ex / (1.f + ex);
        g_gi[2 * warp]     = i0;  g_gi[2 * warp + 1] = i1;
        g_gw[2 * warp]     = g0;  g_gw[2 * warp + 1] = g1;
        atomicAdd(&g_counts[i0], 1);
        atomicAdd(&g_counts[i1], 1);
    }
}

// ---------------- Scan / scatter ---------------------------------------------
__global__ void scan_kernel() {
    if (threadIdx.x == 0) {
        int o = 0;
        for (int e = 0; e < NEXP; e++) {
            g_off[e] = o;
            g_cursor[e] = o;
            o += ((g_counts[e] + (MTILE - 1)) / MTILE) * MTILE;
        }
        g_off[NEXP] = o;
    }
}

__global__ void fill_kernel() {
    int i = blockIdx.x * blockDim.x + threadIdx.x;
    if (i < MAXROWS) g_perm[i] = -1;
}

__global__ void scatter_kernel() {
    int t = blockIdx.x * blockDim.x + threadIdx.x;
    if (t >= T_TOK) return;
    #pragma unroll
    for (int s = 0; s < 2; s++) {
        int e = g_gi[2 * t + s];
        int pos = atomicAdd(&g_cursor[e], 1);
        g_perm[pos] = t;
        g_inv[2 * t + s] = pos;
    }
}

// ---------------- Grouped GEMM: fp16 mma m16n8k16, cp.async 3-stage ----------
// Tile 128x128x32, 8 warps (4M x 2N), warp tile 32x64.
// SMEM: A[128][40] half (80B rows), B[128][40] half, per stage. 3 stages.
#define LSTRIDE 40                       // halves per row (80B, 16B-aligned, conflict-free)
#define A_STAGE_H (128 * LSTRIDE)        // halves
#define B_STAGE_H (128 * LSTRIDE)
#define B_BASE_H  (3 * A_STAGE_H)
#define SMEM_H    (3 * A_STAGE_H + 3 * B_STAGE_H)
#define SMEM_GEMM_BYTES (SMEM_H * 2)

// MODE 1: A = gather(g_xh, perm) [K=1024], B = g_w1h, C = gelu(.+b1) -> g_hh (fp16)
// MODE 2: A = g_hh rows          [K=4096], B = g_w2h, C = .+b2       -> g_y  (fp32)
template <int MODE>
__global__ void __launch_bounds__(256, 2)
gemm_mma(const __half* __restrict__ Bw, const float* __restrict__ bias,
         int Kdim, int Ncols) {
    extern __shared__ __align__(16) __half smh[];

    const int base = blockIdx.y * MTILE;
    if (base >= g_off[NEXP]) return;
    int e = 0;
    while (base >= g_off[e + 1]) e++;
    const int rows_valid = g_off[e] + g_counts[e] - base;
    if (rows_valid <= 0) return;

    const int tid  = threadIdx.x;
    const int lane = tid & 31;
    const int wid  = tid >> 5;
    const int wm = wid & 3;
    const int wn = wid >> 2;
    const int g8   = lane >> 2;   // 0..7
    const int ctid = lane & 3;    // 0..3

    const int ncolbase = blockIdx.x * 128;

    // ---- loaders: 2 threads per row; each thread 2 x 16B segs per chunk
    const int lrow  = tid >> 1;            // 0..127
    const int lseg  = (tid & 1) * 2;       // seg base {0,2}; segs lseg, lseg+1 (16B each)

    const __half* asrc;
    if (MODE == 1) {
        int tok = g_perm[base + lrow];
        if (tok < 0) tok = 0;
        asrc = g_xh + (size_t)tok * DIM;
    } else {
        asrc = g_hh + (size_t)(base + lrow) * HID;
    }
    const __half* bsrc = Bw + ((size_t)e * Ncols + ncolbase + lrow) * Kdim;

    const uint32_t smem_u32 = (uint32_t)__cvta_generic_to_shared(smh);
    // smem byte offsets for this thread's two segments (A region / B region)
    const uint32_t a_off0 = lrow * (LSTRIDE * 2) + lseg * 16;
    const uint32_t b_off0 = B_BASE_H * 2 + lrow * (LSTRIDE * 2) + lseg * 16;

    float acc[2][8][4];
    #pragma unroll
    for (int i = 0; i < 2; i++)
        #pragma unroll
        for (int j = 0; j < 8; j++)
            #pragma unroll
            for (int q = 0; q < 4; q++) acc[i][j][q] = 0.f;

    const int nch = Kdim / 32;

    // prologue: stage chunks 0 and 1
    #pragma unroll
    for (int s = 0; s < 2; s++) {
        const __half* ga = asrc + s * 32 + lseg * 8;
        const __half* gb = bsrc + s * 32 + lseg * 8;
        const uint32_t ao = smem_u32 + s * (A_STAGE_H * 2) + a_off0;
        const uint32_t bo = smem_u32 + s * (B_STAGE_H * 2) + b_off0;
        cp_async16(ao,      ga);
        cp_async16(ao + 16, ga + 8);
        cp_async16(bo,      gb);
        cp_async16(bo + 16, gb + 8);
        CP_COMMIT();
    }

    for (int kc = 0; kc < nch; kc++) {
        CP_WAIT1();
        __syncthreads();

        const int cl = kc + 2;
        if (cl < nch) {
            const int st2 = cl % 3;
            const __half* ga = asrc + cl * 32 + lseg * 8;
            const __half* gb = bsrc + cl * 32 + lseg * 8;
            const uint32_t ao = smem_u32 + st2 * (A_STAGE_H * 2) + a_off0;
            const uint32_t bo = smem_u32 + st2 * (B_STAGE_H * 2) + b_off0;
            cp_async16(ao,      ga);
            cp_async16(ao + 16, ga + 8);
            cp_async16(bo,      gb);
            cp_async16(bo + 16, gb + 8);
        }
        CP_COMMIT();

        const int st = kc % 3;
        const __half* A_s = smh + st * A_STAGE_H;
        const __half* B_s = smh + B_BASE_H + st * B_STAGE_H;

        #pragma unroll
        for (int ks = 0; ks < 2; ks++) {
            const int k0 = ks * 16;
            unsigned afr[2][4], bfr[8][2];
            #pragma unroll
            for (int i = 0; i < 2; i++) {
                const int r = wm * 32 + i * 16;
                afr[i][0] = *reinterpret_cast<const unsigned*>(&A_s[(r + g8)     * LSTRIDE + k0 + ctid * 2]);
                afr[i][1] = *reinterpret_cast<const unsigned*>(&A_s[(r + g8 + 8) * LSTRIDE + k0 + ctid * 2]);
                afr[i][2] = *reinterpret_cast<const unsigned*>(&A_s[(r + g8)     * LSTRIDE + k0 + ctid * 2 + 8]);
                afr[i][3] = *reinterpret_cast<const unsigned*>(&A_s[(r + g8 + 8) * LSTRIDE + k0 + ctid * 2 + 8]);
            }
            #pragma unroll
            for (int j = 0; j < 8; j++) {
                const int c = wn * 64 + j * 8 + g8;
                bfr[j][0] = *reinterpret_cast<const unsigned*>(&B_s[c * LSTRIDE + k0 + ctid * 2]);
                bfr[j][1] = *reinterpret_cast<const unsigned*>(&B_s[c * LSTRIDE + k0 + ctid * 2 + 8]);
            }
            #pragma unroll
            for (int i = 0; i < 2; i++)
                #pragma unroll
                for (int j = 0; j < 8; j++)
                    mma_f16(acc[i][j], afr[i], bfr[j]);
        }
    }
    CP_WAIT0();

    // ---- epilogue
    #pragma unroll
    for (int i = 0; i < 2; i++) {
        const int r0 = wm * 32 + i * 16 + g8;
        #pragma unroll
        for (int j = 0; j < 8; j++) {
            const int c = wn * 64 + j * 8 + ctid * 2;
            const int ng = ncolbase + c;
            const float bv0 = bias[ng], bv1 = bias[ng + 1];

            if (r0 < rows_valid) {
                const int pos = base + r0;
                float v0 = acc[i][j][0] + bv0;
                float v1 = acc[i][j][1] + bv1;
                if (MODE == 1) {
                    v0 *= normcdff(v0); v1 *= normcdff(v1);
                    *reinterpret_cast<__half2*>(g_hh + (size_t)pos * HID + ng) =
                        __floats2half2_rn(v0, v1);
                } else {
                    g_y[(size_t)pos * DIM + ng]     = v0;
                    g_y[(size_t)pos * DIM + ng + 1] = v1;
                }
            }
            if (r0 + 8 < rows_valid) {
                const int pos = base + r0 + 8;
                float v0 = acc[i][j][2] + bv0;
                float v1 = acc[i][j][3] + bv1;
                if (MODE == 1) {
                    v0 *= normcdff(v0); v1 *= normcdff(v1);
                    *reinterpret_cast<__half2*>(g_hh + (size_t)pos * HID + ng) =
                        __floats2half2_rn(v0, v1);
                } else {
                    g_y[(size_t)pos * DIM + ng]     = v0;
                    g_y[(size_t)pos * DIM + ng + 1] = v1;
                }
            }
        }
    }
}

// ---------------- Combine ----------------------------------------------------
__global__ void combine_kernel(const float* __restrict__ x, float* __restrict__ out) {
    int t = blockIdx.x;
    int tid = threadIdx.x;
    float g0 = g_gw[2 * t], g1 = g_gw[2 * t + 1];
    int   p0 = g_inv[2 * t], p1 = g_inv[2 * t + 1];
    int idx = tid * 4;
    float4 xv = *reinterpret_cast<const float4*>(x + (size_t)t * DIM + idx);
    float4 y0 = *reinterpret_cast<const float4*>(g_y + (size_t)p0 * DIM + idx);
    float4 y1 = *reinterpret_cast<const float4*>(g_y + (size_t)p1 * DIM + idx);
    float4 o;
    o.x = xv.x + g0 * y0.x + g1 * y1.x;
    o.y = xv.y + g0 * y0.y + g1 * y1.y;
    o.z = xv.z + g0 * y0.z + g1 * y1.z;
    o.w = xv.w + g0 * y0.w + g1 * y1.w;
    *reinterpret_cast<float4*>(out + (size_t)t * DIM + idx) = o;
}

// ---------------- Balance loss -------------------------------------------------
__global__ void loss_kernel(float* __restrict__ out, int out_size) {
    __shared__ float red[256];
    __shared__ float tot[NEXP];
    int tid = threadIdx.x;
    float s[NEXP];
    #pragma unroll
    for (int q = 0; q < NEXP; q++) s[q] = 0.f;
    for (int i = tid; i < 2 * T_TOK; i += 256) {
        int e = g_gi[i];
        float w = g_gw[i];
        #pragma unroll
        for (int q = 0; q < NEXP; q++) s[q] += (e == q) ? w : 0.f;
    }
    for (int q = 0; q < NEXP; q++) {
        red[tid] = s[q];
        __syncthreads();
        for (int o = 128; o; o >>= 1) {
            if (tid < o) red[tid] += red[tid + o];
            __syncthreads();
        }
        if (tid == 0) tot[q] = red[0];
        __syncthreads();
    }
    if (tid == 0 && out_size > T_TOK * DIM) {
        float l = 0.f;
        #pragma unroll
        for (int q = 0; q < NEXP; q++) {
            float d = tot[q] * (1.f / T_TOK) - (1.f / NEXP);
            l += d * d;
        }
        out[T_TOK * DIM] = l * (1.f / NEXP);
    }
}

// ---------------- launch --------------------------------------------------------
extern "C" void kernel_launch(void* const* d_in, const int* in_sizes, int n_in,
                              void* d_out, int out_size) {
    const float* x      = (const float*)d_in[0];
    const float* gamma  = (const float*)d_in[1];
    const float* beta   = (const float*)d_in[2];
    const float* gate_w = (const float*)d_in[3];
    const float* W1     = (const float*)d_in[4];
    const float* b1     = (const float*)d_in[5];
    const float* W2     = (const float*)d_in[6];
    const float* b2     = (const float*)d_in[7];
    float* out = (float*)d_out;

    cudaFuncSetAttribute(gemm_mma<1>, cudaFuncAttributeMaxDynamicSharedMemorySize, SMEM_GEMM_BYTES);
    cudaFuncSetAttribute(gemm_mma<2>, cudaFuncAttributeMaxDynamicSharedMemorySize, SMEM_GEMM_BYTES);

    __half *w1h, *w2h;
    cudaGetSymbolAddress((void**)&w1h, g_w1h);
    cudaGetSymbolAddress((void**)&w2h, g_w2h);
    transpose_h_kernel<<<dim3(HID / 32, DIM / 32, NEXP), dim3(32, 8)>>>(W1, w1h, DIM, HID);
    transpose_h_kernel<<<dim3(DIM / 32, HID / 32, NEXP), dim3(32, 8)>>>(W2, w2h, HID, DIM);

    init_kernel<<<1, 32>>>();
    ln_kernel<<<T_TOK, 256>>>(x, gamma, beta);
    gate_kernel<<<T_TOK / 8, 256>>>(gate_w);
    scan_kernel<<<1, 1>>>();
    fill_kernel<<<(MAXROWS + 255) / 256, 256>>>();
    scatter_kernel<<<T_TOK / 256, 256>>>();

    gemm_mma<1><<<dim3(HID / 128, MAXMT), 256, SMEM_GEMM_BYTES>>>(w1h, b1, DIM, HID);
    gemm_mma<2><<<dim3(DIM / 128, MAXMT), 256, SMEM_GEMM_BYTES>>>(w2h, b2, HID, DIM);

    combine_kernel<<<T_TOK, 256>>>(x, out);
    loss_kernel<<<1, 256>>>(out, out_size);
}

// round 5
// speedup vs baseline: 2.0256x; 1.1705x over previous
#include <cuda_runtime.h>
#include <cuda_fp16.h>
#include <math.h>
#include <stdint.h>

// Problem constants
#define T_TOK 8192
#define DIM   1024
#define NEXP  8
#define HID   4096
#define MTILE 128
#define MAXROWS 17408            // 16384 + 8*128 pad
#define MAXMT   (MAXROWS / MTILE)

// ---------------- device scratch (static; no cudaMalloc) -------------------
__device__ __half g_xh [(size_t)T_TOK * DIM];      // LN out fp16 (GEMM1 A)
__device__ __half g_hh [(size_t)MAXROWS * HID];    // gelu(x@W1+b1) fp16
__device__ float  g_y  [(size_t)MAXROWS * DIM];    // h@W2+b2 fp32
__device__ __half g_w1h[(size_t)NEXP * DIM * HID]; // W1 -> [e][n(H)][k(D)] fp16
__device__ __half g_w2h[(size_t)NEXP * HID * DIM]; // W2 -> [e][n(D)][k(H)] fp16
__device__ int    g_perm[MAXROWS];
__device__ int    g_inv [T_TOK * 2];
__device__ float  g_gw  [T_TOK * 2];
__device__ int    g_gi  [T_TOK * 2];
__device__ int    g_counts[NEXP];
__device__ int    g_off[NEXP + 1];
__device__ int    g_cursor[NEXP];

// ---------------- helpers ----------------------------------------------------
__device__ __forceinline__ void mma_f16(float* c, const unsigned* a, const unsigned* b) {
    asm volatile(
        "mma.sync.aligned.m16n8k16.row.col.f32.f16.f16.f32 "
        "{%0,%1,%2,%3}, {%4,%5,%6,%7}, {%8,%9}, {%0,%1,%2,%3};\n"
        : "+f"(c[0]), "+f"(c[1]), "+f"(c[2]), "+f"(c[3])
        : "r"(a[0]), "r"(a[1]), "r"(a[2]), "r"(a[3]), "r"(b[0]), "r"(b[1]));
}

__device__ __forceinline__ void ldsm_x4(unsigned& r0, unsigned& r1, unsigned& r2, unsigned& r3,
                                        uint32_t addr) {
    asm volatile("ldmatrix.sync.aligned.m8n8.x4.shared.b16 {%0,%1,%2,%3}, [%4];"
        : "=r"(r0), "=r"(r1), "=r"(r2), "=r"(r3) : "r"(addr));
}

__device__ __forceinline__ void cp_async16(uint32_t saddr, const void* gptr) {
    asm volatile("cp.async.cg.shared.global [%0], [%1], 16;"
        :: "r"(saddr), "l"(__cvta_generic_to_global(gptr)) : "memory");
}
#define CP_COMMIT() asm volatile("cp.async.commit_group;" ::: "memory")
#define CP_WAIT1()  asm volatile("cp.async.wait_group 1;"  ::: "memory")
#define CP_WAIT0()  asm volatile("cp.async.wait_group 0;"  ::: "memory")

// ---------------- init ------------------------------------------------------
__global__ void init_kernel() {
    int i = threadIdx.x;
    if (i < NEXP) g_counts[i] = 0;
}

// ---------------- weight transpose+fp16: [e][k][n] f32 -> [e][n][k] f16 -----
__global__ void transpose_h_kernel(const float* __restrict__ in, __half* __restrict__ out,
                                   int K, int N) {
    __shared__ float t[32][33];
    const size_t eo = (size_t)blockIdx.z * K * N;
    const int n0 = blockIdx.x * 32, k0 = blockIdx.y * 32;
    for (int j = threadIdx.y; j < 32; j += 8)
        t[j][threadIdx.x] = in[eo + (size_t)(k0 + j) * N + n0 + threadIdx.x];
    __syncthreads();
    for (int j = threadIdx.y; j < 32; j += 8)
        out[eo + (size_t)(n0 + j) * K + k0 + threadIdx.x] = __float2half_rn(t[threadIdx.x][j]);
}

// ---------------- Fused LayerNorm + gating ----------------------------------
__global__ void ln_gate_kernel(const float* __restrict__ x,
                               const float* __restrict__ gamma,
                               const float* __restrict__ beta,
                               const float* __restrict__ gate_w) {
    int t = blockIdx.x;
    int tid = threadIdx.x;
    int lane = tid & 31, wrp = tid >> 5;
    const float4 v = *reinterpret_cast<const float4*>(x + (size_t)t * DIM + tid * 4);
    __shared__ float red1[8], red2[8];
    __shared__ float sgate[8][8];
    __shared__ float slog[8];

    float s = v.x + v.y + v.z + v.w;
    #pragma unroll
    for (int o = 16; o; o >>= 1) s += __shfl_xor_sync(0xffffffffu, s, o);
    if (lane == 0) red1[wrp] = s;
    __syncthreads();
    float mu = 0.f;
    #pragma unroll
    for (int i = 0; i < 8; i++) mu += red1[i];
    mu *= (1.f / DIM);

    float dx = v.x - mu, dy = v.y - mu, dz = v.z - mu, dw = v.w - mu;
    float s2 = dx * dx + dy * dy + dz * dz + dw * dw;
    #pragma unroll
    for (int o = 16; o; o >>= 1) s2 += __shfl_xor_sync(0xffffffffu, s2, o);
    if (lane == 0) red2[wrp] = s2;
    __syncthreads();
    float var = 0.f;
    #pragma unroll
    for (int i = 0; i < 8; i++) var += red2[i];
    var *= (1.f / DIM);
    float rstd = rsqrtf(var + 1e-5f);

    const float4 g = *reinterpret_cast<const float4*>(gamma + tid * 4);
    const float4 b = *reinterpret_cast<const float4*>(beta  + tid * 4);
    float4 o;
    o.x = dx * rstd * g.x + b.x;
    o.y = dy * rstd * g.y + b.y;
    o.z = dz * rstd * g.z + b.z;
    o.w = dw * rstd * g.w + b.w;

    __half2 h0 = __floats2half2_rn(o.x, o.y);
    __half2 h1 = __floats2half2_rn(o.z, o.w);
    *reinterpret_cast<__half2*>(g_xh + (size_t)t * DIM + tid * 4)     = h0;
    *reinterpret_cast<__half2*>(g_xh + (size_t)t * DIM + tid * 4 + 2) = h1;

    // gating dot-products (fp32, exact vs reference ordering-insensitive sum)
    float accg[NEXP];
    #pragma unroll
    for (int e = 0; e < NEXP; e++) {
        const float4 w = *reinterpret_cast<const float4*>(gate_w + e * DIM + tid * 4);
        accg[e] = o.x * w.x + o.y * w.y + o.z * w.z + o.w * w.w;
    }
    #pragma unroll
    for (int e = 0; e < NEXP; e++)
        #pragma unroll
        for (int off = 16; off; off >>= 1)
            accg[e] += __shfl_xor_sync(0xffffffffu, accg[e], off);
    if (lane == 0)
        #pragma unroll
        for (int e = 0; e < NEXP; e++) sgate[wrp][e] = accg[e];
    __syncthreads();
    if (tid < NEXP) {
        float l = 0.f;
        #pragma unroll
        for (int w = 0; w < 8; w++) l += sgate[w][tid];
        slog[tid] = l;
    }
    __syncthreads();
    if (tid == 0) {
        int i0 = 0; float v0 = slog[0];
        #pragma unroll
        for (int e = 1; e < NEXP; e++) if (slog[e] > v0) { v0 = slog[e]; i0 = e; }
        int i1 = -1; float v1 = -3.0e38f;
        #pragma unroll
        for (int e = 0; e < NEXP; e++) if (e != i0 && slog[e] > v1) { v1 = slog[e]; i1 = e; }
        float ex = expf(v1 - v0);
        float g0 = 1.f / (1.f + ex);
        float g1 = ex / (1.f + ex);
        g_gi[2 * t]     = i0;  g_gi[2 * t + 1] = i1;
        g_gw[2 * t]     = g0;  g_gw[2 * t + 1] = g1;
        atomicAdd(&g_counts[i0], 1);
        atomicAdd(&g_counts[i1], 1);
    }
}

// ---------------- Scan / scatter ---------------------------------------------
__global__ void scan_kernel() {
    if (threadIdx.x == 0) {
        int o = 0;
        for (int e = 0; e < NEXP; e++) {
            g_off[e] = o;
            g_cursor[e] = o;
            o += ((g_counts[e] + (MTILE - 1)) / MTILE) * MTILE;
        }
        g_off[NEXP] = o;
    }
}

__global__ void fill_kernel() {
    int i = blockIdx.x * blockDim.x + threadIdx.x;
    if (i < MAXROWS) g_perm[i] = -1;
}

__global__ void scatter_kernel() {
    int t = blockIdx.x * blockDim.x + threadIdx.x;
    if (t >= T_TOK) return;
    #pragma unroll
    for (int s = 0; s < 2; s++) {
        int e = g_gi[2 * t + s];
        int pos = atomicAdd(&g_cursor[e], 1);
        g_perm[pos] = t;
        g_inv[2 * t + s] = pos;
    }
}

// ---------------- Grouped GEMM: fp16 mma m16n8k16 + ldmatrix ----------------
// Tile 128x128x32, 8 warps (4M x 2N), warp tile 32x64, 3-stage cp.async.
#define LSTRIDE 40                       // halves per row (80B)
#define A_STAGE_H (128 * LSTRIDE)
#define B_STAGE_H (128 * LSTRIDE)
#define B_BASE_H  (3 * A_STAGE_H)
#define SMEM_H    (3 * A_STAGE_H + 3 * B_STAGE_H)
#define SMEM_GEMM_BYTES (SMEM_H * 2)
#define A_STAGE_B (A_STAGE_H * 2)
#define B_STAGE_B (B_STAGE_H * 2)
#define B_BASE_B  (B_BASE_H * 2)

// MODE 1: A = gather(g_xh, perm) [K=1024], B = g_w1h, C = gelu(.+b1) -> g_hh
// MODE 2: A = g_hh rows          [K=4096], B = g_w2h, C = .+b2       -> g_y
template <int MODE>
__global__ void __launch_bounds__(256, 2)
gemm_mma(const __half* __restrict__ Bw, const float* __restrict__ bias,
         int Kdim, int Ncols) {
    extern __shared__ __align__(16) __half smh[];

    const int base = blockIdx.y * MTILE;
    if (base >= g_off[NEXP]) return;
    int e = 0;
    while (base >= g_off[e + 1]) e++;
    const int rows_valid = g_off[e] + g_counts[e] - base;
    if (rows_valid <= 0) return;

    const int tid  = threadIdx.x;
    const int lane = tid & 31;
    const int wid  = tid >> 5;
    const int wm = wid & 3;
    const int wn = wid >> 2;
    const int g8   = lane >> 2;
    const int ctid = lane & 3;

    const int ncolbase = blockIdx.x * 128;

    // ---- gmem loaders: 2 threads per row; 2 x 16B segs each per chunk
    const int lrow  = tid >> 1;
    const int lseg  = (tid & 1) * 2;

    const __half* asrc;
    if (MODE == 1) {
        int tok = g_perm[base + lrow];
        if (tok < 0) tok = 0;
        asrc = g_xh + (size_t)tok * DIM;
    } else {
        asrc = g_hh + (size_t)(base + lrow) * HID;
    }
    const __half* bsrc = Bw + ((size_t)e * Ncols + ncolbase + lrow) * Kdim;

    const uint32_t smem_u32 = (uint32_t)__cvta_generic_to_shared(smh);
    const uint32_t a_off0 = lrow * (LSTRIDE * 2) + lseg * 16;
    const uint32_t b_off0 = B_BASE_B + lrow * (LSTRIDE * 2) + lseg * 16;

    // ---- ldmatrix per-thread offsets (bytes)
    const int mq = lane >> 3;               // matrix quadrant 0..3
    const int r7 = lane & 7;
    // A: matrix q -> row group (q&1)*8, k seg (q>>1)*8
    const uint32_t aoff = ((wm * 32 + ((mq & 1) << 3) + r7) * LSTRIDE + ((mq >> 1) << 3)) * 2;
    // B: matrix q -> row group (q>>1)*8, k seg (q&1)*8
    const uint32_t boff = B_BASE_B +
        ((wn * 64 + ((mq >> 1) << 3) + r7) * LSTRIDE + ((mq & 1) << 3)) * 2;

    float acc[2][8][4];
    #pragma unroll
    for (int i = 0; i < 2; i++)
        #pragma unroll
        for (int j = 0; j < 8; j++)
            #pragma unroll
            for (int q = 0; q < 4; q++) acc[i][j][q] = 0.f;

    const int nch = Kdim / 32;

    // prologue: stage chunks 0 and 1
    #pragma unroll
    for (int s = 0; s < 2; s++) {
        const __half* ga = asrc + s * 32 + lseg * 8;
        const __half* gb = bsrc + s * 32 + lseg * 8;
        const uint32_t ao = smem_u32 + s * A_STAGE_B + a_off0;
        const uint32_t bo = smem_u32 + s * B_STAGE_B + b_off0;
        cp_async16(ao,      ga);
        cp_async16(ao + 16, ga + 8);
        cp_async16(bo,      gb);
        cp_async16(bo + 16, gb + 8);
        CP_COMMIT();
    }

    for (int kc = 0; kc < nch; kc++) {
        CP_WAIT1();
        __syncthreads();

        const int cl = kc + 2;
        if (cl < nch) {
            const int st2 = cl % 3;
            const __half* ga = asrc + cl * 32 + lseg * 8;
            const __half* gb = bsrc + cl * 32 + lseg * 8;
            const uint32_t ao = smem_u32 + st2 * A_STAGE_B + a_off0;
            const uint32_t bo = smem_u32 + st2 * B_STAGE_B + b_off0;
            cp_async16(ao,      ga);
            cp_async16(ao + 16, ga + 8);
            cp_async16(bo,      gb);
            cp_async16(bo + 16, gb + 8);
        }
        CP_COMMIT();

        const int st = kc % 3;
        const uint32_t aBase = smem_u32 + st * A_STAGE_B + aoff;
        const uint32_t bBase = smem_u32 + st * B_STAGE_B + boff;

        #pragma unroll
        for (int ks = 0; ks < 2; ks++) {
            unsigned afr[2][4], bfr[8][2];
            #pragma unroll
            for (int i = 0; i < 2; i++)
                ldsm_x4(afr[i][0], afr[i][1], afr[i][2], afr[i][3],
                        aBase + i * (16 * LSTRIDE * 2) + ks * 32);
            #pragma unroll
            for (int jp = 0; jp < 4; jp++) {
                unsigned r0, r1, r2, r3;
                ldsm_x4(r0, r1, r2, r3, bBase + jp * (16 * LSTRIDE * 2) + ks * 32);
                bfr[2 * jp][0] = r0; bfr[2 * jp][1] = r1;
                bfr[2 * jp + 1][0] = r2; bfr[2 * jp + 1][1] = r3;
            }
            #pragma unroll
            for (int i = 0; i < 2; i++)
                #pragma unroll
                for (int j = 0; j < 8; j++)
                    mma_f16(acc[i][j], afr[i], bfr[j]);
        }
    }
    CP_WAIT0();

    // ---- epilogue
    #pragma unroll
    for (int i = 0; i < 2; i++) {
        const int r0 = wm * 32 + i * 16 + g8;
        #pragma unroll
        for (int j = 0; j < 8; j++) {
            const int c = wn * 64 + j * 8 + ctid * 2;
            const int ng = ncolbase + c;
            const float bv0 = bias[ng], bv1 = bias[ng + 1];

            if (r0 < rows_valid) {
                const int pos = base + r0;
                float v0 = acc[i][j][0] + bv0;
                float v1 = acc[i][j][1] + bv1;
                if (MODE == 1) {
                    v0 *= normcdff(v0); v1 *= normcdff(v1);
                    *reinterpret_cast<__half2*>(g_hh + (size_t)pos * HID + ng) =
                        __floats2half2_rn(v0, v1);
                } else {
                    g_y[(size_t)pos * DIM + ng]     = v0;
                    g_y[(size_t)pos * DIM + ng + 1] = v1;
                }
            }
            if (r0 + 8 < rows_valid) {
                const int pos = base + r0 + 8;
                float v0 = acc[i][j][2] + bv0;
                float v1 = acc[i][j][3] + bv1;
                if (MODE == 1) {
                    v0 *= normcdff(v0); v1 *= normcdff(v1);
                    *reinterpret_cast<__half2*>(g_hh + (size_t)pos * HID + ng) =
                        __floats2half2_rn(v0, v1);
                } else {
                    g_y[(size_t)pos * DIM + ng]     = v0;
                    g_y[(size_t)pos * DIM + ng + 1] = v1;
                }
            }
        }
    }
}

// ---------------- Combine ----------------------------------------------------
__global__ void combine_kernel(const float* __restrict__ x, float* __restrict__ out) {
    int t = blockIdx.x;
    int tid = threadIdx.x;
    float g0 = g_gw[2 * t], g1 = g_gw[2 * t + 1];
    int   p0 = g_inv[2 * t], p1 = g_inv[2 * t + 1];
    int idx = tid * 4;
    float4 xv = *reinterpret_cast<const float4*>(x + (size_t)t * DIM + idx);
    float4 y0 = *reinterpret_cast<const float4*>(g_y + (size_t)p0 * DIM + idx);
    float4 y1 = *reinterpret_cast<const float4*>(g_y + (size_t)p1 * DIM + idx);
    float4 o;
    o.x = xv.x + g0 * y0.x + g1 * y1.x;
    o.y = xv.y + g0 * y0.y + g1 * y1.y;
    o.z = xv.z + g0 * y0.z + g1 * y1.z;
    o.w = xv.w + g0 * y0.w + g1 * y1.w;
    *reinterpret_cast<float4*>(out + (size_t)t * DIM + idx) = o;
}

// ---------------- Balance loss -------------------------------------------------
__global__ void loss_kernel(float* __restrict__ out, int out_size) {
    __shared__ float red[256];
    __shared__ float tot[NEXP];
    int tid = threadIdx.x;
    float s[NEXP];
    #pragma unroll
    for (int q = 0; q < NEXP; q++) s[q] = 0.f;
    for (int i = tid; i < 2 * T_TOK; i += 256) {
        int e = g_gi[i];
        float w = g_gw[i];
        #pragma unroll
        for (int q = 0; q < NEXP; q++) s[q] += (e == q) ? w : 0.f;
    }
    for (int q = 0; q < NEXP; q++) {
        red[tid] = s[q];
        __syncthreads();
        for (int o = 128; o; o >>= 1) {
            if (tid < o) red[tid] += red[tid + o];
            __syncthreads();
        }
        if (tid == 0) tot[q] = red[0];
        __syncthreads();
    }
    if (tid == 0 && out_size > T_TOK * DIM) {
        float l = 0.f;
        #pragma unroll
        for (int q = 0; q < NEXP; q++) {
            float d = tot[q] * (1.f / T_TOK) - (1.f / NEXP);
            l += d * d;
        }
        out[T_TOK * DIM] = l * (1.f / NEXP);
    }
}

// ---------------- launch --------------------------------------------------------
extern "C" void kernel_launch(void* const* d_in, const int* in_sizes, int n_in,
                              void* d_out, int out_size) {
    const float* x      = (const float*)d_in[0];
    const float* gamma  = (const float*)d_in[1];
    const float* beta   = (const float*)d_in[2];
    const float* gate_w = (const float*)d_in[3];
    const float* W1     = (const float*)d_in[4];
    const float* b1     = (const float*)d_in[5];
    const float* W2     = (const float*)d_in[6];
    const float* b2     = (const float*)d_in[7];
    float* out = (float*)d_out;

    cudaFuncSetAttribute(gemm_mma<1>, cudaFuncAttributeMaxDynamicSharedMemorySize, SMEM_GEMM_BYTES);
    cudaFuncSetAttribute(gemm_mma<2>, cudaFuncAttributeMaxDynamicSharedMemorySize, SMEM_GEMM_BYTES);

    __half *w1h, *w2h;
    cudaGetSymbolAddress((void**)&w1h, g_w1h);
    cudaGetSymbolAddress((void**)&w2h, g_w2h);
    transpose_h_kernel<<<dim3(HID / 32, DIM / 32, NEXP), dim3(32, 8)>>>(W1, w1h, DIM, HID);
    transpose_h_kernel<<<dim3(DIM / 32, HID / 32, NEXP), dim3(32, 8)>>>(W2, w2h, HID, DIM);

    init_kernel<<<1, 32>>>();
    ln_gate_kernel<<<T_TOK, 256>>>(x, gamma, beta, gate_w);
    scan_kernel<<<1, 1>>>();
    fill_kernel<<<(MAXROWS + 255) / 256, 256>>>();
    scatter_kernel<<<T_TOK / 256, 256>>>();

    gemm_mma<1><<<dim3(HID / 128, MAXMT), 256, SMEM_GEMM_BYTES>>>(w1h, b1, DIM, HID);
    gemm_mma<2><<<dim3(DIM / 128, MAXMT), 256, SMEM_GEMM_BYTES>>>(w2h, b2, HID, DIM);

    combine_kernel<<<T_TOK, 256>>>(x, out);
    loss_kernel<<<1, 256>>>(out, out_size);
}